// round 12
// baseline (speedup 1.0000x reference)
#include <cuda_runtime.h>

#define TPB 128
#define W   1116

__device__ __forceinline__ float softf(float c, float t) {
    return copysignf(fmaxf(fabsf(c) - t, 0.0f), c);
}

// Shared layout (floats), all bases 16B-aligned:
//  [0..571]      eA (front pad 4 -> data at 4)      \  forward set A (levels 2,4,6 src)
//  [572..1143]   oA (front pad 4 -> data at 576)    /
//  [1144..1439]  eB (front pad 4 -> data at 1148)   \  forward set B (levels 1,3,5 src)
//  [1440..1735]  oB (front pad 4 -> data at 1444)   /
//  [1736..1755]  a7 (final approx, linear, 15 used)
//  [1756..2915]  sD (all detail levels, 4-aligned regions)
//  Inverse aliases: lin0 = sm+0 (<=1120), lin1 = sm+1120 (<=616 slack)
__global__ void __launch_bounds__(TPB, 8) wavelet_kernel(
    const float* __restrict__ x, const float* __restrict__ rawthr,
    float* __restrict__ out)
{
    constexpr float DLO[8] = {
        -0.010597401784997278f,  0.032883011666982945f,
         0.030841381835986965f, -0.18703481171888114f,
        -0.02798376941698385f,   0.6308807679295904f,
         0.7148465705525415f,    0.23037781330885523f };
    // DHI[j] = (-1)^(j+1) * DLO[7-j]
    constexpr float DHI[8] = {
        -0.23037781330885523f,   0.7148465705525415f,
        -0.6308807679295904f,   -0.02798376941698385f,
         0.18703481171888114f,   0.030841381835986965f,
        -0.032883011666982945f, -0.010597401784997278f };

    constexpr int NS[8]   = {1116, 561, 284, 145, 76, 41, 24, 15};
    constexpr int DOFF[7] = {0, 564, 848, 996, 1072, 1116, 1140};

    __shared__ __align__(16) float sm[2916];
    float* const EP[2] = { sm + 4,   sm + 1148 };
    float* const OP[2] = { sm + 576, sm + 1444 };
    float* const a7 = sm + 1736;
    float* const sD = sm + 1756;

    const int tid = threadIdx.x;
    const long row = blockIdx.x;
    const float thr = fmaxf(rawthr[0], 0.01f);

    // front pads of both e/o sets (set A needed for level-2 windows, set B for level-1)
    if (tid < 4) { sm[tid] = 0.f; sm[572 + tid] = 0.f; sm[1144 + tid] = 0.f; sm[1440 + tid] = 0.f; }
    __syncthreads();

    // ---- Forward level 0: directly from global, 4 outputs/thread ----
    // ca[4g+k] = sum_j DLO[j] * w[2k+9-j],  w[n] = x[8g-8+n], n=0..15
    {
        const float* xr = x + row * W;
        float* de  = EP[1];
        float* do_ = OP[1];
        float* dd  = sD + DOFF[0];
        const int nout = 561;           // groups 0..140

        for (int g = tid; g < 141; g += TPB) {
            float w[16];
            if (g >= 1 && g <= 138) {   // full in-bounds window: x[8g-8 .. 8g+7]
                const float4* wp = (const float4*)(xr + 8 * g - 8);
                float4 X0 = wp[0], X1 = wp[1], X2 = wp[2], X3 = wp[3];
                w[0]=X0.x; w[1]=X0.y; w[2]=X0.z; w[3]=X0.w;
                w[4]=X1.x; w[5]=X1.y; w[6]=X1.z; w[7]=X1.w;
                w[8]=X2.x; w[9]=X2.y; w[10]=X2.z; w[11]=X2.w;
                w[12]=X3.x; w[13]=X3.y; w[14]=X3.z; w[15]=X3.w;
            } else {                    // g==0, 139, 140: zero-padded boundary
                #pragma unroll
                for (int n = 0; n < 16; n++) {
                    int ix = 8 * g - 8 + n;
                    w[n] = (ix >= 0 && ix < W) ? xr[ix] : 0.f;
                }
            }

            float ca[4], cd[4];
            #pragma unroll
            for (int k = 0; k < 4; k++) {
                float a = 0.f, d = 0.f;
                #pragma unroll
                for (int j = 0; j < 8; j++) {
                    float v = w[2 * k + 9 - j];
                    a = fmaf(DLO[j], v, a);
                    d = fmaf(DHI[j], v, d);
                }
                ca[k] = a;
                cd[k] = softf(d, thr);
            }

            if (4 * g + 3 < nout) {
                *(float4*)(dd + 4 * g) = make_float4(cd[0], cd[1], cd[2], cd[3]);
                *(float2*)(de  + 2 * g) = make_float2(ca[0], ca[2]);
                *(float2*)(do_ + 2 * g) = make_float2(ca[1], ca[3]);
            } else {                    // g==140: i=560 only
                #pragma unroll
                for (int k = 0; k < 4; k++) {
                    int i = 4 * g + k;
                    if (i < nout) {
                        dd[i] = cd[k];
                        if (i & 1) do_[i >> 1] = ca[k];
                        else       de[i >> 1]  = ca[k];
                    }
                }
            }
        }
        // tail pads of set B for level-1 windows (ec=281, oc=280)
        if (tid < 8) { de[281 + tid] = 0.f; do_[280 + tid] = 0.f; }
        __syncthreads();
    }

    // ---- Forward levels 1..6 in smem, 4 outputs/thread ----
    #pragma unroll
    for (int l = 1; l < 7; l++) {
        const int nout = NS[l + 1];
        const float* se = EP[l & 1];
        const float* so = OP[l & 1];
        float* de  = EP[(l + 1) & 1];
        float* do_ = OP[(l + 1) & 1];
        float* dd  = sD + DOFF[l];
        const int groups = (nout + 3) >> 2;

        for (int g = tid; g < groups; g += TPB) {
            float4 E0 = *(const float4*)(se + 4 * g - 4);
            float4 E1 = *(const float4*)(se + 4 * g);
            float4 O0 = *(const float4*)(so + 4 * g - 4);
            float4 O1 = *(const float4*)(so + 4 * g);
            float we[8] = {E0.x, E0.y, E0.z, E0.w, E1.x, E1.y, E1.z, E1.w};
            float wo[8] = {O0.x, O0.y, O0.z, O0.w, O1.x, O1.y, O1.z, O1.w};

            float ca[4], cd[4];
            #pragma unroll
            for (int k = 0; k < 4; k++) {
                float a = 0.f, d = 0.f;
                #pragma unroll
                for (int m = 0; m < 4; m++) {
                    float ev = we[k + 4 - m], ov = wo[k + 4 - m];
                    a = fmaf(DLO[2 * m + 1],  ev, a);
                    a = fmaf(DLO[2 * m],      ov, a);
                    d = fmaf(DLO[6 - 2 * m],  ev, d);
                    d = fmaf(-DLO[7 - 2 * m], ov, d);
                }
                ca[k] = a;
                cd[k] = softf(d, thr);
            }

            if (4 * g + 3 < nout) {
                *(float4*)(dd + 4 * g) = make_float4(cd[0], cd[1], cd[2], cd[3]);
                if (l < 6) {
                    *(float2*)(de  + 2 * g) = make_float2(ca[0], ca[2]);
                    *(float2*)(do_ + 2 * g) = make_float2(ca[1], ca[3]);
                } else {
                    *(float4*)(a7 + 4 * g) = make_float4(
                        softf(ca[0], thr), softf(ca[1], thr),
                        softf(ca[2], thr), softf(ca[3], thr));
                }
            } else {
                #pragma unroll
                for (int k = 0; k < 4; k++) {
                    int i = 4 * g + k;
                    if (i < nout) {
                        dd[i] = cd[k];
                        if (l < 6) {
                            if (i & 1) do_[i >> 1] = ca[k];
                            else       de[i >> 1]  = ca[k];
                        } else {
                            a7[i] = softf(ca[k], thr);
                        }
                    }
                }
            }
        }
        if (l < 6 && tid < 8) {
            const int ec = (nout + 1) >> 1, oc = nout >> 1;
            de[ec + tid]  = 0.f;
            do_[oc + tid] = 0.f;
        }
        __syncthreads();
    }

    // ---- Inverse: levels s=6..1 in smem, 2 pairs/thread ----
    float* const lin0 = sm;
    float* const lin1 = sm + 1120;

    #pragma unroll
    for (int s = 6; s >= 1; s--) {
        const int n = NS[s + 1];
        const float* a = (s == 6) ? a7 : ((((5 - s) & 1)) ? lin1 : lin0);
        float* dst     = (((6 - s) & 1)) ? lin1 : lin0;
        const float* d = sD + DOFF[s];
        const int pairs  = n - 3;
        const int groups = (pairs + 1) >> 1;

        for (int g = tid; g < groups; g += TPB) {
            float2 A0 = *(const float2*)(a + 2 * g);
            float2 A1 = *(const float2*)(a + 2 * g + 2);
            float2 A2 = *(const float2*)(a + 2 * g + 4);
            float2 D0 = *(const float2*)(d + 2 * g);
            float2 D1 = *(const float2*)(d + 2 * g + 2);
            float2 D2 = *(const float2*)(d + 2 * g + 4);
            float wa[5] = {A0.x, A0.y, A1.x, A1.y, A2.x};
            float wd[5] = {D0.x, D0.y, D1.x, D1.y, D2.x};

            float ye0 = 0.f, yo0 = 0.f, ye1 = 0.f, yo1 = 0.f;
            #pragma unroll
            for (int q = 0; q < 4; q++) {
                ye0 = fmaf(DLO[7 - 2 * q],  wa[3 - q], ye0);
                ye0 = fmaf(DLO[2 * q],      wd[3 - q], ye0);
                yo0 = fmaf(DLO[6 - 2 * q],  wa[3 - q], yo0);
                yo0 = fmaf(-DLO[2 * q + 1], wd[3 - q], yo0);
                ye1 = fmaf(DLO[7 - 2 * q],  wa[4 - q], ye1);
                ye1 = fmaf(DLO[2 * q],      wd[4 - q], ye1);
                yo1 = fmaf(DLO[6 - 2 * q],  wa[4 - q], yo1);
                yo1 = fmaf(-DLO[2 * q + 1], wd[4 - q], yo1);
            }

            if (2 * g + 1 < pairs) {
                *(float4*)(dst + 4 * g) = make_float4(ye0, yo0, ye1, yo1);
            } else {
                *(float2*)(dst + 4 * g) = make_float2(ye0, yo0);
            }
        }
        __syncthreads();
    }

    // ---- Inverse s=0: 2 pairs/thread, straight to global (558 pairs = 1116 floats) ----
    {
        const float* a = lin1;          // s=1 result (length 562, use 561)
        const float* d = sD;            // DOFF[0] = 0, length 561
        float* orow = out + row * W;
        const int groups = 279;

        for (int g = tid; g < groups; g += TPB) {
            float2 A0 = *(const float2*)(a + 2 * g);
            float2 A1 = *(const float2*)(a + 2 * g + 2);
            float2 A2 = *(const float2*)(a + 2 * g + 4);
            float2 D0 = *(const float2*)(d + 2 * g);
            float2 D1 = *(const float2*)(d + 2 * g + 2);
            float2 D2 = *(const float2*)(d + 2 * g + 4);
            float wa[5] = {A0.x, A0.y, A1.x, A1.y, A2.x};
            float wd[5] = {D0.x, D0.y, D1.x, D1.y, D2.x};

            float ye0 = 0.f, yo0 = 0.f, ye1 = 0.f, yo1 = 0.f;
            #pragma unroll
            for (int q = 0; q < 4; q++) {
                ye0 = fmaf(DLO[7 - 2 * q],  wa[3 - q], ye0);
                ye0 = fmaf(DLO[2 * q],      wd[3 - q], ye0);
                yo0 = fmaf(DLO[6 - 2 * q],  wa[3 - q], yo0);
                yo0 = fmaf(-DLO[2 * q + 1], wd[3 - q], yo0);
                ye1 = fmaf(DLO[7 - 2 * q],  wa[4 - q], ye1);
                ye1 = fmaf(DLO[2 * q],      wd[4 - q], ye1);
                yo1 = fmaf(DLO[6 - 2 * q],  wa[4 - q], yo1);
                yo1 = fmaf(-DLO[2 * q + 1], wd[4 - q], yo1);
            }

            *(float4*)(orow + 4 * g) = make_float4(ye0, yo0, ye1, yo1);
        }
    }
}

extern "C" void kernel_launch(void* const* d_in, const int* in_sizes, int n_in,
                              void* d_out, int out_size) {
    const float* x   = (const float*)d_in[0];
    const float* thr = (const float*)d_in[1];
    float* out = (float*)d_out;
    const int rows = in_sizes[0] / W;
    wavelet_kernel<<<rows, TPB>>>(x, thr, out);
}

// round 14
// speedup vs baseline: 1.0031x; 1.0031x over previous
#include <cuda_runtime.h>

#define TPB 128
#define W   1116

__device__ __forceinline__ float softf(float c, float t) {
    return copysignf(fmaxf(fabsf(c) - t, 0.0f), c);
}

// Shared layout (floats), all bases 16B-aligned:
//  [0..571]      eA (front pad 4 -> data at 4)      \  forward set A (levels 2,4,6 src)
//  [572..1143]   oA (front pad 4 -> data at 576)    /
//  [1144..1439]  eB (front pad 4 -> data at 1148)   \  forward set B (levels 1,3,5 src)
//  [1440..1735]  oB (front pad 4 -> data at 1444)   /
//  [1736..1755]  a7 (final approx, linear, 15 used)
//  [1756..2915]  sD (all detail levels, 4-aligned regions)
//  Inverse aliases: lin0 = sm+0 (<=1120), lin1 = sm+1120 (<=616 slack)
__global__ void __launch_bounds__(TPB, 8) wavelet_kernel(
    const float* __restrict__ x, const float* __restrict__ rawthr,
    float* __restrict__ out)
{
    constexpr float DLO[8] = {
        -0.010597401784997278f,  0.032883011666982945f,
         0.030841381835986965f, -0.18703481171888114f,
        -0.02798376941698385f,   0.6308807679295904f,
         0.7148465705525415f,    0.23037781330885523f };
    // DHI[j] = (-1)^(j+1) * DLO[7-j]
    constexpr float DHI[8] = {
        -0.23037781330885523f,   0.7148465705525415f,
        -0.6308807679295904f,   -0.02798376941698385f,
         0.18703481171888114f,   0.030841381835986965f,
        -0.032883011666982945f, -0.010597401784997278f };

    constexpr int NS[8]   = {1116, 561, 284, 145, 76, 41, 24, 15};
    constexpr int DOFF[7] = {0, 564, 848, 996, 1072, 1116, 1140};

    __shared__ __align__(16) float sm[2916];
    float* const EP[2] = { sm + 4,   sm + 1148 };
    float* const OP[2] = { sm + 576, sm + 1444 };
    float* const a7 = sm + 1736;
    float* const sD = sm + 1756;

    const int tid = threadIdx.x;
    const long row = blockIdx.x;
    const float thr = fmaxf(rawthr[0], 0.01f);

    // front pads of both e/o sets
    if (tid < 4) { sm[tid] = 0.f; sm[572 + tid] = 0.f; sm[1144 + tid] = 0.f; sm[1440 + tid] = 0.f; }
    __syncthreads();

    // ---- Forward level 0: directly from global, phase-split to cap registers ----
    // ca[4g+k] = sum_j DLO[j] * w[2k+9-j],  w[n] = x[8g-8+n]
    {
        const float* xr = x + row * W;
        float* de  = EP[1];
        float* do_ = OP[1];
        float* dd  = sD;                 // DOFF[0] = 0

        // main vector groups g = 1..138 (windows fully in-bounds)
        for (int g = tid + 1; g <= 138; g += TPB) {
            const float* wp = xr + 8 * g - 8;
            float4 X0 = *(const float4*)(wp);
            float4 X1 = *(const float4*)(wp + 4);
            float wA[8] = {X0.x, X0.y, X0.z, X0.w, X1.x, X1.y, X1.z, X1.w};

            float a[4] = {0.f, 0.f, 0.f, 0.f};
            float d[4] = {0.f, 0.f, 0.f, 0.f};
            // Phase A: taps touching w[2..7]
            #pragma unroll
            for (int k = 0; k < 4; k++) {
                #pragma unroll
                for (int n = 2 * k + 2; n < 8; n++) {
                    const int j = 2 * k + 9 - n;
                    a[k] = fmaf(DLO[j], wA[n], a[k]);
                    d[k] = fmaf(DHI[j], wA[n], d[k]);
                }
            }
            // Fake dependency: force the second pair of loads to issue after
            // phase A's accumulator exists (caps the live window at 8 floats).
            float dep = a[0];
            asm volatile("" : "+f"(dep));
            const float* wp2 = wp + 8 + ((__float_as_int(dep) >> 31) & 0); // +0, data-dep on dep
            float4 X2 = *(const float4*)(wp2);
            float4 X3 = *(const float4*)(wp2 + 4);
            float wB[8] = {X2.x, X2.y, X2.z, X2.w, X3.x, X3.y, X3.z, X3.w};
            // Phase B: taps touching w[8..15]
            #pragma unroll
            for (int k = 0; k < 4; k++) {
                #pragma unroll
                for (int n = 8; n <= 2 * k + 9; n++) {
                    const int j = 2 * k + 9 - n;
                    a[k] = fmaf(DLO[j], wB[n - 8], a[k]);
                    d[k] = fmaf(DHI[j], wB[n - 8], d[k]);
                }
            }

            *(float4*)(dd + 4 * g) = make_float4(
                softf(d[0], thr), softf(d[1], thr), softf(d[2], thr), softf(d[3], thr));
            *(float2*)(de  + 2 * g) = make_float2(a[0], a[2]);
            *(float2*)(do_ + 2 * g) = make_float2(a[1], a[3]);
        }

        // boundary outputs: i in {0,1,2,3} u {556..560}  (9 outputs, scalar)
        if (tid < 9) {
            const int i = (tid < 4) ? tid : (552 + tid);
            float a = 0.f, dv = 0.f;
            #pragma unroll
            for (int j = 0; j < 8; j++) {
                const int ix = 2 * i + 1 - j;
                const float v = (ix >= 0 && ix < W) ? xr[ix] : 0.f;
                a  = fmaf(DLO[j], v, a);
                dv = fmaf(DHI[j], v, dv);
            }
            dd[i] = softf(dv, thr);
            if (i & 1) do_[i >> 1] = a;
            else       de[i >> 1]  = a;
        }
        // tail pads of set B for level-1 windows (ec=281, oc=280)
        if (tid < 8) { de[281 + tid] = 0.f; do_[280 + tid] = 0.f; }
        __syncthreads();
    }

    // ---- Forward levels 1..6 in smem, 4 outputs/thread (R10 geometry) ----
    #pragma unroll
    for (int l = 1; l < 7; l++) {
        const int nout = NS[l + 1];
        const float* se = EP[l & 1];
        const float* so = OP[l & 1];
        float* de  = EP[(l + 1) & 1];
        float* do_ = OP[(l + 1) & 1];
        float* dd  = sD + DOFF[l];
        const int groups = (nout + 3) >> 2;

        for (int g = tid; g < groups; g += TPB) {
            float4 E0 = *(const float4*)(se + 4 * g - 4);
            float4 E1 = *(const float4*)(se + 4 * g);
            float4 O0 = *(const float4*)(so + 4 * g - 4);
            float4 O1 = *(const float4*)(so + 4 * g);
            float we[8] = {E0.x, E0.y, E0.z, E0.w, E1.x, E1.y, E1.z, E1.w};
            float wo[8] = {O0.x, O0.y, O0.z, O0.w, O1.x, O1.y, O1.z, O1.w};

            float ca[4], cd[4];
            #pragma unroll
            for (int k = 0; k < 4; k++) {
                float a = 0.f, d = 0.f;
                #pragma unroll
                for (int m = 0; m < 4; m++) {
                    float ev = we[k + 4 - m], ov = wo[k + 4 - m];
                    a = fmaf(DLO[2 * m + 1],  ev, a);
                    a = fmaf(DLO[2 * m],      ov, a);
                    d = fmaf(DLO[6 - 2 * m],  ev, d);
                    d = fmaf(-DLO[7 - 2 * m], ov, d);
                }
                ca[k] = a;
                cd[k] = softf(d, thr);
            }

            if (4 * g + 3 < nout) {
                *(float4*)(dd + 4 * g) = make_float4(cd[0], cd[1], cd[2], cd[3]);
                if (l < 6) {
                    *(float2*)(de  + 2 * g) = make_float2(ca[0], ca[2]);
                    *(float2*)(do_ + 2 * g) = make_float2(ca[1], ca[3]);
                } else {
                    *(float4*)(a7 + 4 * g) = make_float4(
                        softf(ca[0], thr), softf(ca[1], thr),
                        softf(ca[2], thr), softf(ca[3], thr));
                }
            } else {
                #pragma unroll
                for (int k = 0; k < 4; k++) {
                    int i = 4 * g + k;
                    if (i < nout) {
                        dd[i] = cd[k];
                        if (l < 6) {
                            if (i & 1) do_[i >> 1] = ca[k];
                            else       de[i >> 1]  = ca[k];
                        } else {
                            a7[i] = softf(ca[k], thr);
                        }
                    }
                }
            }
        }
        if (l < 6 && tid < 8) {
            const int ec = (nout + 1) >> 1, oc = nout >> 1;
            de[ec + tid]  = 0.f;
            do_[oc + tid] = 0.f;
        }
        __syncthreads();
    }

    // ---- Inverse: levels s=6..1 in smem, 2 pairs/thread (R10 geometry) ----
    float* const lin0 = sm;
    float* const lin1 = sm + 1120;

    #pragma unroll
    for (int s = 6; s >= 1; s--) {
        const int n = NS[s + 1];
        const float* a = (s == 6) ? a7 : ((((5 - s) & 1)) ? lin1 : lin0);
        float* dst     = (((6 - s) & 1)) ? lin1 : lin0;
        const float* d = sD + DOFF[s];
        const int pairs  = n - 3;
        const int groups = (pairs + 1) >> 1;

        for (int g = tid; g < groups; g += TPB) {
            float2 A0 = *(const float2*)(a + 2 * g);
            float2 A1 = *(const float2*)(a + 2 * g + 2);
            float2 A2 = *(const float2*)(a + 2 * g + 4);
            float2 D0 = *(const float2*)(d + 2 * g);
            float2 D1 = *(const float2*)(d + 2 * g + 2);
            float2 D2 = *(const float2*)(d + 2 * g + 4);
            float wa[5] = {A0.x, A0.y, A1.x, A1.y, A2.x};
            float wd[5] = {D0.x, D0.y, D1.x, D1.y, D2.x};

            float ye0 = 0.f, yo0 = 0.f, ye1 = 0.f, yo1 = 0.f;
            #pragma unroll
            for (int q = 0; q < 4; q++) {
                ye0 = fmaf(DLO[7 - 2 * q],  wa[3 - q], ye0);
                ye0 = fmaf(DLO[2 * q],      wd[3 - q], ye0);
                yo0 = fmaf(DLO[6 - 2 * q],  wa[3 - q], yo0);
                yo0 = fmaf(-DLO[2 * q + 1], wd[3 - q], yo0);
                ye1 = fmaf(DLO[7 - 2 * q],  wa[4 - q], ye1);
                ye1 = fmaf(DLO[2 * q],      wd[4 - q], ye1);
                yo1 = fmaf(DLO[6 - 2 * q],  wa[4 - q], yo1);
                yo1 = fmaf(-DLO[2 * q + 1], wd[4 - q], yo1);
            }

            if (2 * g + 1 < pairs) {
                *(float4*)(dst + 4 * g) = make_float4(ye0, yo0, ye1, yo1);
            } else {
                *(float2*)(dst + 4 * g) = make_float2(ye0, yo0);
            }
        }
        __syncthreads();
    }

    // ---- Inverse s=0: 4 pairs/thread, straight to global (558 pairs = 1116 floats) ----
    {
        const float* a = lin1;          // s=1 result (length 562, use 561)
        const float* d = sD;            // level-0 details, length 561
        float* orow = out + row * W;

        for (int t = tid; t < 140; t += TPB) {
            if (t < 139) {              // full group: pairs 4t..4t+3
                float4 A0 = *(const float4*)(a + 4 * t);
                float4 A1 = *(const float4*)(a + 4 * t + 4);
                float4 D0 = *(const float4*)(d + 4 * t);
                float4 D1 = *(const float4*)(d + 4 * t + 4);
                float wa[8] = {A0.x,A0.y,A0.z,A0.w, A1.x,A1.y,A1.z,A1.w};
                float wd[8] = {D0.x,D0.y,D0.z,D0.w, D1.x,D1.y,D1.z,D1.w};

                // first half: pairs r=0,1
                {
                    float y0 = 0.f, y1 = 0.f, y2 = 0.f, y3 = 0.f;
                    #pragma unroll
                    for (int q = 0; q < 4; q++) {
                        float av0 = wa[3 - q], dv0 = wd[3 - q];
                        float av1 = wa[4 - q], dv1 = wd[4 - q];
                        y0 = fmaf(DLO[7 - 2 * q],  av0, y0);
                        y0 = fmaf(DLO[2 * q],      dv0, y0);
                        y1 = fmaf(DLO[6 - 2 * q],  av0, y1);
                        y1 = fmaf(-DLO[2 * q + 1], dv0, y1);
                        y2 = fmaf(DLO[7 - 2 * q],  av1, y2);
                        y2 = fmaf(DLO[2 * q],      dv1, y2);
                        y3 = fmaf(DLO[6 - 2 * q],  av1, y3);
                        y3 = fmaf(-DLO[2 * q + 1], dv1, y3);
                    }
                    *(float4*)(orow + 8 * t) = make_float4(y0, y1, y2, y3);
                }
                // second half: pairs r=2,3
                {
                    float y0 = 0.f, y1 = 0.f, y2 = 0.f, y3 = 0.f;
                    #pragma unroll
                    for (int q = 0; q < 4; q++) {
                        float av0 = wa[5 - q], dv0 = wd[5 - q];
                        float av1 = wa[6 - q], dv1 = wd[6 - q];
                        y0 = fmaf(DLO[7 - 2 * q],  av0, y0);
                        y0 = fmaf(DLO[2 * q],      dv0, y0);
                        y1 = fmaf(DLO[6 - 2 * q],  av0, y1);
                        y1 = fmaf(-DLO[2 * q + 1], dv0, y1);
                        y2 = fmaf(DLO[7 - 2 * q],  av1, y2);
                        y2 = fmaf(DLO[2 * q],      dv1, y2);
                        y3 = fmaf(DLO[6 - 2 * q],  av1, y3);
                        y3 = fmaf(-DLO[2 * q + 1], dv1, y3);
                    }
                    *(float4*)(orow + 8 * t + 4) = make_float4(y0, y1, y2, y3);
                }
            } else {                    // t == 139: pairs 556, 557 (outputs 1112..1115)
                #pragma unroll
                for (int r = 0; r < 2; r++) {
                    const int p = 556 + r;
                    float ye = 0.f, yo = 0.f;
                    #pragma unroll
                    for (int q = 0; q < 4; q++) {
                        float av = a[p + 3 - q], dv = d[p + 3 - q];
                        ye = fmaf(DLO[7 - 2 * q],  av, ye);
                        ye = fmaf(DLO[2 * q],      dv, ye);
                        yo = fmaf(DLO[6 - 2 * q],  av, yo);
                        yo = fmaf(-DLO[2 * q + 1], dv, yo);
                    }
                    *(float2*)(orow + 2 * p) = make_float2(ye, yo);
                }
            }
        }
    }
}

extern "C" void kernel_launch(void* const* d_in, const int* in_sizes, int n_in,
                              void* d_out, int out_size) {
    const float* x   = (const float*)d_in[0];
    const float* thr = (const float*)d_in[1];
    float* out = (float*)d_out;
    const int rows = in_sizes[0] / W;
    wavelet_kernel<<<rows, TPB>>>(x, thr, out);
}